// round 13
// baseline (speedup 1.0000x reference)
#include <cuda_runtime.h>

// Problem constants (from reference)
#define G_ 4096
#define U_ 50
#define M_ 20
#define D_ 64
#define S_ 64
#define FACTOR_ 0.5f

// 25 warps = 50 half-warp slots = one user per slot, single pass.
#define NWARPS 25
#define NTHREADS (NWARPS * 32)   // 800

__global__ __launch_bounds__(NTHREADS, 2)
void group_embedding_kernel(const int*   __restrict__ group_user,      // [G,U]
                            const int*   __restrict__ behavior_ids,    // [G,U,M]
                            const float* __restrict__ behavior_counts, // [G,U,M]
                            const int*   __restrict__ target_user,     // [G]
                            const float* __restrict__ similarity_vec,  // [100000,S]
                            const float* __restrict__ user_emb_w,      // [100000,D]
                            const float* __restrict__ item_emb_w,      // [100000,D]
                            float*       __restrict__ out)             // [G,D]
{
    const int g    = blockIdx.x;
    const int tid  = threadIdx.x;
    const int warp = tid >> 5;
    const int lane = tid & 31;
    const int half = lane >> 4;     // which user of the warp's pair
    const int hl   = lane & 15;     // lane owns dims 4*hl..4*hl+3
    const int slot = warp * 2 + half;   // 0..49 == user index

    __shared__ __align__(16) float  partials[NWARPS][D_]; // 6.4KB (warp-folded)
    __shared__ __align__(16) float  red[8][D_];           // 2KB
    __shared__ __align__(16) float2 wbeh[NWARPS][2 * M_]; // per-warp (id,count), 8KB

    // ---- Per-warp staging: this warp's 2 users' 40 (id,count) pairs ----
    {
        const int base = g * (U_ * M_) + warp * (2 * M_);
        wbeh[warp][lane] = make_float2(__int_as_float(behavior_ids[base + lane]),
                                       behavior_counts[base + lane]);
        if (lane < 8)
            wbeh[warp][32 + lane] =
                make_float2(__int_as_float(behavior_ids[base + 32 + lane]),
                            behavior_counts[base + 32 + lane]);
    }
    __syncwarp();   // own warp's wbeh slice ready

    // ---- Gather loop FIRST, minimal register residency.
    const float4* pf4 = reinterpret_cast<const float4*>(&wbeh[warp][half * M_]);
    float4 ub = make_float4(0.f, 0.f, 0.f, 0.f);
    #pragma unroll
    for (int mb = 0; mb < M_ / 2; mb++) {
        const float4 p = pf4[mb];     // (id0, c0, id1, c1)
        const float4 e0 = __ldg(reinterpret_cast<const float4*>(
            item_emb_w + (size_t)__float_as_int(p.x) * D_ + 4 * hl));
        const float4 e1 = __ldg(reinterpret_cast<const float4*>(
            item_emb_w + (size_t)__float_as_int(p.z) * D_ + 4 * hl));
        ub.x += e0.x * p.y;  ub.y += e0.y * p.y;
        ub.z += e0.z * p.y;  ub.w += e0.w * p.y;
        ub.x += e1.x * p.w;  ub.y += e1.y * p.w;
        ub.z += e1.z * p.w;  ub.w += e1.w * p.w;
    }

    // ---- Per-user metadata (after the hot loop).
    const int uid = group_user[g * U_ + slot];

    const float4 ue = *reinterpret_cast<const float4*>(
        user_emb_w + (size_t)uid * D_ + 4 * hl);

    const int tgt = target_user[g];
    const float4 tsim = *reinterpret_cast<const float4*>(
        similarity_vec + (size_t)tgt * S_ + 4 * hl);
    const float4 osim = *reinterpret_cast<const float4*>(
        similarity_vec + (size_t)uid * S_ + 4 * hl);
    float dot = tsim.x * osim.x + tsim.y * osim.y
              + tsim.z * osim.z + tsim.w * osim.w;
    #pragma unroll
    for (int o = 8; o; o >>= 1)
        dot += __shfl_xor_sync(0xffffffffu, dot, o);
    const float sim = FACTOR_ * dot;

    float4 acc;
    acc.x = ub.x * ue.x * sim;
    acc.y = ub.y * ue.y * sim;
    acc.z = ub.z * ue.z * sim;
    acc.w = ub.w * ue.w * sim;

    // ---- Warp-level pair fold: merge half 1's user into half 0's lanes.
    // Lane l and lane l^16 hold the SAME dims (4*hl..4*hl+3) for the two
    // users of this warp; xor-shuffle by 16 and add folds them.
    acc.x += __shfl_xor_sync(0xffffffffu, acc.x, 16);
    acc.y += __shfl_xor_sync(0xffffffffu, acc.y, 16);
    acc.z += __shfl_xor_sync(0xffffffffu, acc.z, 16);
    acc.w += __shfl_xor_sync(0xffffffffu, acc.w, 16);

    if (half == 0)
        *reinterpret_cast<float4*>(&partials[warp][4 * hl]) = acc;
    __syncthreads();

    // ---- Two-stage deterministic reduce over 25 warp rows ----
    // Stage 1: 512 threads = 8 rows x 64 dims; row r sums rows r, r+8, r+16 (+24 for r==0).
    if (tid < 512) {
        const int d = tid & 63;
        const int r = tid >> 6;      // 0..7
        float s = 0.f;
        #pragma unroll
        for (int p = r; p < NWARPS; p += 8)
            s += partials[p][d];
        red[r][d] = s;
    }
    __syncthreads();

    // Stage 2: 64 threads fold the 8 rows.
    if (tid < D_) {
        float s = 0.f;
        #pragma unroll
        for (int r = 0; r < 8; r++)
            s += red[r][tid];
        out[(size_t)g * D_ + tid] = s;
    }
}

extern "C" void kernel_launch(void* const* d_in, const int* in_sizes, int n_in,
                              void* d_out, int out_size) {
    const int*   group_user      = (const int*)  d_in[0];
    const int*   behavior_ids    = (const int*)  d_in[1];
    const float* behavior_counts = (const float*)d_in[2];
    const int*   target_user     = (const int*)  d_in[3];
    const float* similarity_vec  = (const float*)d_in[4];
    const float* user_emb_w      = (const float*)d_in[5];
    const float* item_emb_w      = (const float*)d_in[6];
    float* out = (float*)d_out;

    group_embedding_kernel<<<G_, NTHREADS>>>(
        group_user, behavior_ids, behavior_counts, target_user,
        similarity_vec, user_emb_w, item_emb_w, out);
}